// round 6
// baseline (speedup 1.0000x reference)
#include <cuda_runtime.h>

// Problem constants
#define NQPTS 4096
#define HID   1024
#define RR    4096   // R*K = R*R = 64*64
#define NPTS  16384
#define SUBS  128    // k1 sub-blocks per MLP
#define HC2   32     // k2 h-chunks (32 rows each)

// ---------------- scratch (device globals; no allocation allowed) ----------
__device__ __align__(16) float g_part[2][SUBS][HID]; // per-block partial t-sums
__device__ float g_ysum[2][SUBS];                    // per-block partial y-sums
__device__ __align__(16) float g_Spart[2][HC2][RR];  // h-chunked partial S
__device__ __align__(16) float g_S[2][RR];           // reduced S0, S1
__device__ __align__(16) float g_r[RR];              // rhs flattened [64*64]
__device__ __align__(16) float g_v[HID];             // Wx2 @ r
__device__ float g_c;                                // bx2 . r

__device__ __forceinline__ float tanh_fast(float x) {
    float y;
    asm("tanh.approx.f32 %0, %1;" : "=f"(y) : "f"(x));
    return y;
}

// Forced-order loads: volatile asm pins issue order -> guaranteed deep MLP.
__device__ __forceinline__ float4 ldg4(const float4* p) {
    float4 v;
    asm volatile("ld.global.nc.v4.f32 {%0,%1,%2,%3}, [%4];"
                 : "=f"(v.x), "=f"(v.y), "=f"(v.z), "=f"(v.w) : "l"(p));
    return v;
}
__device__ __forceinline__ float ldgf(const float* p) {
    float v;
    asm volatile("ld.global.nc.f32 %0, [%1];" : "=f"(v) : "l"(p));
    return v;
}

// ---------------------------------------------------------------------------
// K1: per quad point i: y_i = exp(-eq*||x||^2); accumulate
//     t[h] += y_i * tanh(x_i . W[:,h] + b[h]) into per-block partials.
// grid: 256 blocks (2 MLPs x 128 sub-blocks of 32 points), 256 threads.
// ---------------------------------------------------------------------------
__global__ void k1_quad(const float* __restrict__ qx0, const float* __restrict__ qx1,
                        const float* __restrict__ Wq0a, const float* __restrict__ bq0a,
                        const float* __restrict__ Wq1a, const float* __restrict__ bq1a,
                        const float* __restrict__ eq)
{
    const int blk = blockIdx.x;
    const int mlp = blk >> 7;
    const int sub = blk & (SUBS - 1);
    const float* __restrict__ qx = mlp ? qx1 : qx0;
    const float* __restrict__ W  = mlp ? Wq1a : Wq0a;
    const float* __restrict__ B  = mlp ? bq1a : bq0a;
    const int P = NQPTS / SUBS;         // 32 points per block
    const int base = sub * P;
    const int tid = threadIdx.x;

    __shared__ float sx0[32], sx1[32], sx2[32], sy[32];
    if (tid < P) {
        float x0 = qx[(base + tid) * 3 + 0];
        float x1 = qx[(base + tid) * 3 + 1];
        float x2 = qx[(base + tid) * 3 + 2];
        sx0[tid] = x0; sx1[tid] = x1; sx2[tid] = x2;
        sy[tid]  = __expf(-eq[0] * (x0 * x0 + x1 * x1 + x2 * x2));
    }
    __syncthreads();

    float w0[4], w1[4], w2[4], bb[4], acc[4];
#pragma unroll
    for (int k = 0; k < 4; k++) {
        int h = tid + 256 * k;
        w0[k] = W[h]; w1[k] = W[HID + h]; w2[k] = W[2 * HID + h];
        bb[k] = B[h];
        acc[k] = 0.0f;
    }
#pragma unroll 4
    for (int p = 0; p < P; p++) {
        float x0 = sx0[p], x1 = sx1[p], x2 = sx2[p], y = sy[p];
#pragma unroll
        for (int k = 0; k < 4; k++) {
            float a = fmaf(x0, w0[k], fmaf(x1, w1[k], fmaf(x2, w2[k], bb[k])));
            acc[k] = fmaf(y, tanh_fast(a), acc[k]);
        }
    }
#pragma unroll
    for (int k = 0; k < 4; k++)
        g_part[mlp][sub][tid + 256 * k] = acc[k];
    if (tid == 0) {
        float s = 0.0f;
#pragma unroll
        for (int p = 0; p < P; p++) s += sy[p];
        g_ysum[mlp][sub] = s;
    }
}

// ---------------------------------------------------------------------------
// K2: Spart[hc][j] = sum_{h in 32-row chunk} t[h]*Wqb[h,j] (+ ys*bqb[j] hc==0)
// grid: 512 blocks (2 MLPs x 32 h-chunks x 8 j-chunks(512 cols)), 128 thr.
// Forced 8-deep LDG.128 batches for the W stream.
// ---------------------------------------------------------------------------
__global__ void __launch_bounds__(128)
k2_S(const float* __restrict__ Wq0b, const float* __restrict__ bq0b,
     const float* __restrict__ Wq1b, const float* __restrict__ bq1b)
{
    const int blk = blockIdx.x;       // 0..511
    const int mlp = blk >> 8;
    const int rest = blk & 255;
    const int hc = rest >> 3;         // 0..31 (32 rows each)
    const int jc = rest & 7;          // 0..7  (512 cols each)
    const float* __restrict__ W = mlp ? Wq1b : Wq0b;
    const float* __restrict__ B = mlp ? bq1b : bq0b;
    const int tid = threadIdx.x;      // 0..127
    const int hbase = hc * 32;

    __shared__ float tp[4][32];
    __shared__ float t[32];
    __shared__ float sys;

    // ---- t reduction: 4 threads per h, 32 subs each, forced 8-deep loads ---
    {
        const int q = tid >> 5;       // 0..3
        const int h = tid & 31;
        const float* p = &g_part[mlp][q * 32][hbase + h];
        float s = 0.0f;
#pragma unroll
        for (int b = 0; b < 4; b++) {
            float v[8];
#pragma unroll
            for (int u = 0; u < 8; u++)
                v[u] = ldgf(p + (size_t)(b * 8 + u) * HID);
#pragma unroll
            for (int u = 0; u < 8; u++) s += v[u];
        }
        tp[q][h] = s;
    }
    __syncthreads();
    if (tid < 32) t[tid] = tp[0][tid] + tp[1][tid] + tp[2][tid] + tp[3][tid];
    if (hc == 0 && tid >= 64 && tid < 96) {
        int l = tid - 64;
        float s = g_ysum[mlp][l] + g_ysum[mlp][l + 32] +
                  g_ysum[mlp][l + 64] + g_ysum[mlp][l + 96];
#pragma unroll
        for (int o = 16; o; o >>= 1) s += __shfl_xor_sync(0xffffffffu, s, o);
        if (l == 0) sys = s;
    }
    __syncthreads();

    const int j0 = jc * 512 + tid * 4;
    float a0, a1, a2, a3;
    if (hc == 0) {
        float ys = sys;
        a0 = ys * B[j0]; a1 = ys * B[j0 + 1]; a2 = ys * B[j0 + 2]; a3 = ys * B[j0 + 3];
    } else {
        a0 = a1 = a2 = a3 = 0.0f;
    }
    const float4* __restrict__ W4 =
        (const float4*)W + (size_t)hbase * (RR / 4) + (j0 >> 2);

#pragma unroll
    for (int b = 0; b < 4; b++) {
        float4 w[8];
#pragma unroll
        for (int u = 0; u < 8; u++)
            w[u] = ldg4(W4 + (size_t)(b * 8 + u) * (RR / 4));
#pragma unroll
        for (int u = 0; u < 8; u++) {
            float th = t[b * 8 + u];
            a0 = fmaf(th, w[u].x, a0);
            a1 = fmaf(th, w[u].y, a1);
            a2 = fmaf(th, w[u].z, a2);
            a3 = fmaf(th, w[u].w, a3);
        }
    }
    *((float4*)&g_Spart[mlp][hc][j0]) = make_float4(a0, a1, a2, a3);
}

// ---------------------------------------------------------------------------
// K2b: reduce g_Spart (32 chunks) -> g_S.  16 blocks x 128 threads,
// one float4 output per thread, forced 8-deep loads.
// ---------------------------------------------------------------------------
__global__ void __launch_bounds__(128)
k2b_reduce()
{
    const int j4 = blockIdx.x * 128 + threadIdx.x;   // 0..2047
    const int mlp = j4 >> 10;
    const int col = j4 & 1023;
    const float4* __restrict__ base =
        (const float4*)g_Spart + (size_t)mlp * HC2 * (RR / 4) + col;
    float4 a = make_float4(0.f, 0.f, 0.f, 0.f);
#pragma unroll
    for (int b = 0; b < 4; b++) {
        float4 v[8];
#pragma unroll
        for (int u = 0; u < 8; u++)
            v[u] = ldg4(base + (size_t)(b * 8 + u) * (RR / 4));
#pragma unroll
        for (int u = 0; u < 8; u++) {
            a.x += v[u].x; a.y += v[u].y; a.z += v[u].z; a.w += v[u].w;
        }
    }
    ((float4*)g_S)[j4] = a;
}

// ---------------------------------------------------------------------------
// K3: r[b*64+d] = sum_x S0[b,x]*S1[d,x].  16 blocks x 256 threads,
// each block: 4 b-rows x 64 d. S1 staged padded; S0 4 rows staged.
// ---------------------------------------------------------------------------
__global__ void k3_rhs()
{
    __shared__ float s1[64 * 65];
    __shared__ float s0[4 * 65];
    const int tid = threadIdx.x;   // 0..255
    const int bbase = blockIdx.x * 4;

    // stage S1 (full, padded pitch 65)
#pragma unroll
    for (int k = 0; k < 16; k++) {
        int j = k * 256 + tid;
        s1[(j >> 6) * 65 + (j & 63)] = g_S[1][j];
    }
    // stage S0 rows bbase..bbase+3
    if (tid < 256) {
        int b = tid >> 6, x = tid & 63;
        s0[b * 65 + x] = g_S[0][(bbase + b) * 64 + x];
    }
    __syncthreads();

    const int b = tid >> 6;        // 0..3
    const int d = tid & 63;
    float acc = 0.0f;
#pragma unroll 16
    for (int x = 0; x < 64; x++)
        acc = fmaf(s0[b * 65 + x], s1[d * 65 + x], acc);
    g_r[(bbase + b) * 64 + d] = acc;
}

// ---------------------------------------------------------------------------
// K4: v[h] = Wx2[h,:] . r  (blocks 0..511, 2 rows each, r staged in smem,
// forced 8-deep W batches).  Block 512 computes c = bx2 . r.
// ---------------------------------------------------------------------------
__global__ void __launch_bounds__(256)
k4_v(const float* __restrict__ Wx2, const float* __restrict__ bx2)
{
    const int tid = threadIdx.x;

    if (blockIdx.x == 512) {    // c = bx2 . r
        const float4* __restrict__ b4 = (const float4*)bx2;
        const float4* __restrict__ r4 = (const float4*)g_r;
        float acc = 0.0f;
#pragma unroll
        for (int k = 0; k < 4; k++) {
            float4 b = ldg4(b4 + tid + 256 * k);
            float4 r = ldg4(r4 + tid + 256 * k);
            acc += b.x * r.x + b.y * r.y + b.z * r.z + b.w * r.w;
        }
#pragma unroll
        for (int o = 16; o; o >>= 1) acc += __shfl_xor_sync(0xffffffffu, acc, o);
        __shared__ float red[8];
        if ((tid & 31) == 0) red[tid >> 5] = acc;
        __syncthreads();
        if (tid == 0) {
            float s = 0.0f;
#pragma unroll
            for (int i = 0; i < 8; i++) s += red[i];
            g_c = s;
        }
        return;
    }

    __shared__ float4 sr[RR / 4];     // 16 KB
    const float4* __restrict__ r4 = (const float4*)g_r;
#pragma unroll
    for (int k = 0; k < 4; k++)
        sr[tid + 256 * k] = r4[tid + 256 * k];
    __syncthreads();

    const int row = tid >> 7;                      // 0 or 1
    const int h = blockIdx.x * 2 + row;
    const int g = tid & 127;
    const float4* __restrict__ W4 = (const float4*)Wx2 + (size_t)h * (RR / 4) + g;

    float4 w[8];
#pragma unroll
    for (int k = 0; k < 8; k++)
        w[k] = ldg4(W4 + 128 * k);
    float acc = 0.0f;
#pragma unroll
    for (int k = 0; k < 8; k++) {
        float4 rr = sr[g + 128 * k];
        acc = fmaf(w[k].x, rr.x, acc);
        acc = fmaf(w[k].y, rr.y, acc);
        acc = fmaf(w[k].z, rr.z, acc);
        acc = fmaf(w[k].w, rr.w, acc);
    }
#pragma unroll
    for (int o = 16; o; o >>= 1) acc += __shfl_xor_sync(0xffffffffu, acc, o);
    __shared__ float part[8];
    if ((tid & 31) == 0) part[tid >> 5] = acc;
    __syncthreads();
    if (tid < 2)
        g_v[blockIdx.x * 2 + tid] = part[4 * tid] + part[4 * tid + 1] +
                                    part[4 * tid + 2] + part[4 * tid + 3];
}

// ---------------------------------------------------------------------------
// K5: out[n] = tanh(input[n] @ Wx1 + bx1) . v + c
// grid: 512 blocks x 256 threads; warp handles 4 rows n (reuses smem loads 4x)
// ---------------------------------------------------------------------------
__global__ void k5_out(const float* __restrict__ input, const float* __restrict__ Wx1,
                       const float* __restrict__ bx1, float* __restrict__ out)
{
    __shared__ float4 swb[HID];   // (w0, w1, w2, bias)
    __shared__ float  sv[HID];
    const int tid = threadIdx.x;
#pragma unroll
    for (int k = 0; k < 4; k++) {
        int h = tid + 256 * k;
        swb[h] = make_float4(Wx1[h], Wx1[HID + h], Wx1[2 * HID + h], bx1[h]);
        sv[h] = g_v[h];
    }
    __syncthreads();

    const int warp = tid >> 5, lane = tid & 31;
    const int nbase = (blockIdx.x * 8 + warp) * 4;

    float x0[4], x1[4], x2[4];
#pragma unroll
    for (int nn = 0; nn < 4; nn++) {
        x0[nn] = input[(nbase + nn) * 3 + 0];
        x1[nn] = input[(nbase + nn) * 3 + 1];
        x2[nn] = input[(nbase + nn) * 3 + 2];
    }
    float acc[4] = {0.0f, 0.0f, 0.0f, 0.0f};
#pragma unroll 4
    for (int k = 0; k < 32; k++) {
        int h = k * 32 + lane;
        float4 wb = swb[h];
        float vv = sv[h];
#pragma unroll
        for (int nn = 0; nn < 4; nn++) {
            float a = fmaf(x0[nn], wb.x, fmaf(x1[nn], wb.y, fmaf(x2[nn], wb.z, wb.w)));
            acc[nn] = fmaf(tanh_fast(a), vv, acc[nn]);
        }
    }
    float c = g_c;
#pragma unroll
    for (int nn = 0; nn < 4; nn++) {
        float a = acc[nn];
#pragma unroll
        for (int o = 16; o; o >>= 1) a += __shfl_xor_sync(0xffffffffu, a, o);
        if (lane == 0) out[nbase + nn] = a + c;
    }
}

// ---------------------------------------------------------------------------
// Input order (metadata): 0 input, 1 eq_param, 2 quad_x0, 3 quad_x1,
// 4 Wx1, 5 bx1, 6 Wx2, 7 bx2, 8 Wq0a, 9 bq0a, 10 Wq0b, 11 bq0b,
// 12 Wq1a, 13 bq1a, 14 Wq1b, 15 bq1b
// ---------------------------------------------------------------------------
extern "C" void kernel_launch(void* const* d_in, const int* in_sizes, int n_in,
                              void* d_out, int out_size)
{
    const float* input  = (const float*)d_in[0];
    const float* eq     = (const float*)d_in[1];
    const float* qx0    = (const float*)d_in[2];
    const float* qx1    = (const float*)d_in[3];
    const float* Wx1    = (const float*)d_in[4];
    const float* bx1    = (const float*)d_in[5];
    const float* Wx2    = (const float*)d_in[6];
    const float* bx2    = (const float*)d_in[7];
    const float* Wq0a   = (const float*)d_in[8];
    const float* bq0a   = (const float*)d_in[9];
    const float* Wq0b   = (const float*)d_in[10];
    const float* bq0b   = (const float*)d_in[11];
    const float* Wq1a   = (const float*)d_in[12];
    const float* bq1a   = (const float*)d_in[13];
    const float* Wq1b   = (const float*)d_in[14];
    const float* bq1b   = (const float*)d_in[15];
    float* out = (float*)d_out;

    k1_quad<<<256, 256>>>(qx0, qx1, Wq0a, bq0a, Wq1a, bq1a, eq);
    k2_S<<<512, 128>>>(Wq0b, bq0b, Wq1b, bq1b);
    k2b_reduce<<<16, 128>>>();
    k3_rhs<<<16, 256>>>();
    k4_v<<<513, 256>>>(Wx2, bx2);
    k5_out<<<512, 256>>>(input, Wx1, bx1, out);
}

// round 7
// speedup vs baseline: 1.0077x; 1.0077x over previous
#include <cuda_runtime.h>

// Problem constants
#define NQPTS 4096
#define HID   1024
#define RR    4096   // R*K = R*R = 64*64
#define NPTS  16384
#define SUBS  128    // k1 sub-blocks per MLP
#define HC2   32     // k2 h-chunks (32 rows each)

// ---------------- scratch (device globals; no allocation allowed) ----------
__device__ __align__(16) float g_part[2][SUBS][HID]; // per-block partial t-sums
__device__ float g_ysum[2][SUBS];                    // per-block partial y-sums
__device__ __align__(16) float g_Spart[2][HC2][RR];  // h-chunked partial S
__device__ __align__(16) float g_S[2][RR];           // reduced S0, S1
__device__ __align__(16) float g_r[RR];              // rhs flattened [64*64]
__device__ __align__(16) float g_v[HID];             // Wx2 @ r
__device__ float g_c;                                // bx2 . r

__device__ __forceinline__ float tanh_fast(float x) {
    float y;
    asm("tanh.approx.f32 %0, %1;" : "=f"(y) : "f"(x));
    return y;
}

// Forced-order loads: volatile asm pins issue order -> guaranteed deep MLP.
__device__ __forceinline__ float4 ldg4(const float4* p) {
    float4 v;
    asm volatile("ld.global.nc.v4.f32 {%0,%1,%2,%3}, [%4];"
                 : "=f"(v.x), "=f"(v.y), "=f"(v.z), "=f"(v.w) : "l"(p));
    return v;
}
__device__ __forceinline__ float ldgf(const float* p) {
    float v;
    asm volatile("ld.global.nc.f32 %0, [%1];" : "=f"(v) : "l"(p));
    return v;
}

// ---------------------------------------------------------------------------
// K1: per quad point i: y_i = exp(-eq*||x||^2); accumulate
//     t[h] += y_i * tanh(x_i . W[:,h] + b[h]) into per-block partials.
// grid: 256 blocks (2 MLPs x 128 sub-blocks of 32 points), 256 threads.
// ---------------------------------------------------------------------------
__global__ void k1_quad(const float* __restrict__ qx0, const float* __restrict__ qx1,
                        const float* __restrict__ Wq0a, const float* __restrict__ bq0a,
                        const float* __restrict__ Wq1a, const float* __restrict__ bq1a,
                        const float* __restrict__ eq)
{
    const int blk = blockIdx.x;
    const int mlp = blk >> 7;
    const int sub = blk & (SUBS - 1);
    const float* __restrict__ qx = mlp ? qx1 : qx0;
    const float* __restrict__ W  = mlp ? Wq1a : Wq0a;
    const float* __restrict__ B  = mlp ? bq1a : bq0a;
    const int P = NQPTS / SUBS;         // 32 points per block
    const int base = sub * P;
    const int tid = threadIdx.x;

    __shared__ float sx0[32], sx1[32], sx2[32], sy[32];
    if (tid < P) {
        float x0 = qx[(base + tid) * 3 + 0];
        float x1 = qx[(base + tid) * 3 + 1];
        float x2 = qx[(base + tid) * 3 + 2];
        sx0[tid] = x0; sx1[tid] = x1; sx2[tid] = x2;
        sy[tid]  = __expf(-eq[0] * (x0 * x0 + x1 * x1 + x2 * x2));
    }
    __syncthreads();

    float w0[4], w1[4], w2[4], bb[4], acc[4];
#pragma unroll
    for (int k = 0; k < 4; k++) {
        int h = tid + 256 * k;
        w0[k] = W[h]; w1[k] = W[HID + h]; w2[k] = W[2 * HID + h];
        bb[k] = B[h];
        acc[k] = 0.0f;
    }
#pragma unroll 4
    for (int p = 0; p < P; p++) {
        float x0 = sx0[p], x1 = sx1[p], x2 = sx2[p], y = sy[p];
#pragma unroll
        for (int k = 0; k < 4; k++) {
            float a = fmaf(x0, w0[k], fmaf(x1, w1[k], fmaf(x2, w2[k], bb[k])));
            acc[k] = fmaf(y, tanh_fast(a), acc[k]);
        }
    }
#pragma unroll
    for (int k = 0; k < 4; k++)
        g_part[mlp][sub][tid + 256 * k] = acc[k];
    if (tid == 0) {
        float s = 0.0f;
#pragma unroll
        for (int p = 0; p < P; p++) s += sy[p];
        g_ysum[mlp][sub] = s;
    }
}

// ---------------------------------------------------------------------------
// K2: Spart[hc][j] = sum_{h in 32-row chunk} t[h]*Wqb[h,j] (+ ys*bqb[j] hc==0)
// grid: 512 blocks (2 MLPs x 32 h-chunks x 8 j-chunks(512 cols)), 128 thr.
// Forced 8-deep LDG.128 batches for the W stream.
// ---------------------------------------------------------------------------
__global__ void __launch_bounds__(128)
k2_S(const float* __restrict__ Wq0b, const float* __restrict__ bq0b,
     const float* __restrict__ Wq1b, const float* __restrict__ bq1b)
{
    const int blk = blockIdx.x;       // 0..511
    const int mlp = blk >> 8;
    const int rest = blk & 255;
    const int hc = rest >> 3;         // 0..31 (32 rows each)
    const int jc = rest & 7;          // 0..7  (512 cols each)
    const float* __restrict__ W = mlp ? Wq1b : Wq0b;
    const float* __restrict__ B = mlp ? bq1b : bq0b;
    const int tid = threadIdx.x;      // 0..127
    const int hbase = hc * 32;

    __shared__ float tp[4][32];
    __shared__ float t[32];
    __shared__ float sys;

    // ---- t reduction: 4 threads per h, 32 subs each, forced 8-deep loads ---
    {
        const int q = tid >> 5;       // 0..3
        const int h = tid & 31;
        const float* p = &g_part[mlp][q * 32][hbase + h];
        float s = 0.0f;
#pragma unroll
        for (int b = 0; b < 4; b++) {
            float v[8];
#pragma unroll
            for (int u = 0; u < 8; u++)
                v[u] = ldgf(p + (size_t)(b * 8 + u) * HID);
#pragma unroll
            for (int u = 0; u < 8; u++) s += v[u];
        }
        tp[q][h] = s;
    }
    __syncthreads();
    if (tid < 32) t[tid] = tp[0][tid] + tp[1][tid] + tp[2][tid] + tp[3][tid];
    if (hc == 0 && tid >= 64 && tid < 96) {
        int l = tid - 64;
        float s = g_ysum[mlp][l] + g_ysum[mlp][l + 32] +
                  g_ysum[mlp][l + 64] + g_ysum[mlp][l + 96];
#pragma unroll
        for (int o = 16; o; o >>= 1) s += __shfl_xor_sync(0xffffffffu, s, o);
        if (l == 0) sys = s;
    }
    __syncthreads();

    const int j0 = jc * 512 + tid * 4;
    float a0, a1, a2, a3;
    if (hc == 0) {
        float ys = sys;
        a0 = ys * B[j0]; a1 = ys * B[j0 + 1]; a2 = ys * B[j0 + 2]; a3 = ys * B[j0 + 3];
    } else {
        a0 = a1 = a2 = a3 = 0.0f;
    }
    const float4* __restrict__ W4 =
        (const float4*)W + (size_t)hbase * (RR / 4) + (j0 >> 2);

#pragma unroll
    for (int b = 0; b < 4; b++) {
        float4 w[8];
#pragma unroll
        for (int u = 0; u < 8; u++)
            w[u] = ldg4(W4 + (size_t)(b * 8 + u) * (RR / 4));
#pragma unroll
        for (int u = 0; u < 8; u++) {
            float th = t[b * 8 + u];
            a0 = fmaf(th, w[u].x, a0);
            a1 = fmaf(th, w[u].y, a1);
            a2 = fmaf(th, w[u].z, a2);
            a3 = fmaf(th, w[u].w, a3);
        }
    }
    *((float4*)&g_Spart[mlp][hc][j0]) = make_float4(a0, a1, a2, a3);
}

// ---------------------------------------------------------------------------
// K2b: reduce g_Spart (32 chunks) -> g_S.  16 blocks x 128 threads,
// one float4 output per thread, forced 8-deep loads.
// ---------------------------------------------------------------------------
__global__ void __launch_bounds__(128)
k2b_reduce()
{
    const int j4 = blockIdx.x * 128 + threadIdx.x;   // 0..2047
    const int mlp = j4 >> 10;
    const int col = j4 & 1023;
    const float4* __restrict__ base =
        (const float4*)g_Spart + (size_t)mlp * HC2 * (RR / 4) + col;
    float4 a = make_float4(0.f, 0.f, 0.f, 0.f);
#pragma unroll
    for (int b = 0; b < 4; b++) {
        float4 v[8];
#pragma unroll
        for (int u = 0; u < 8; u++)
            v[u] = ldg4(base + (size_t)(b * 8 + u) * (RR / 4));
#pragma unroll
        for (int u = 0; u < 8; u++) {
            a.x += v[u].x; a.y += v[u].y; a.z += v[u].z; a.w += v[u].w;
        }
    }
    ((float4*)g_S)[j4] = a;
}

// ---------------------------------------------------------------------------
// K3: r[b*64+d] = sum_x S0[b,x]*S1[d,x].  16 blocks x 256 threads,
// each block: 4 b-rows x 64 d. S1 staged padded; S0 4 rows staged.
// ---------------------------------------------------------------------------
__global__ void k3_rhs()
{
    __shared__ float s1[64 * 65];
    __shared__ float s0[4 * 65];
    const int tid = threadIdx.x;   // 0..255
    const int bbase = blockIdx.x * 4;

    // stage S1 (full, padded pitch 65)
#pragma unroll
    for (int k = 0; k < 16; k++) {
        int j = k * 256 + tid;
        s1[(j >> 6) * 65 + (j & 63)] = g_S[1][j];
    }
    // stage S0 rows bbase..bbase+3
    if (tid < 256) {
        int b = tid >> 6, x = tid & 63;
        s0[b * 65 + x] = g_S[0][(bbase + b) * 64 + x];
    }
    __syncthreads();

    const int b = tid >> 6;        // 0..3
    const int d = tid & 63;
    float acc = 0.0f;
#pragma unroll 16
    for (int x = 0; x < 64; x++)
        acc = fmaf(s0[b * 65 + x], s1[d * 65 + x], acc);
    g_r[(bbase + b) * 64 + d] = acc;
}

// ---------------------------------------------------------------------------
// K4: v[h] = Wx2[h,:] . r  (blocks 0..511, 2 rows each, r staged in smem,
// forced 8-deep W batches).  Block 512 computes c = bx2 . r.
// ---------------------------------------------------------------------------
__global__ void __launch_bounds__(256)
k4_v(const float* __restrict__ Wx2, const float* __restrict__ bx2)
{
    const int tid = threadIdx.x;

    if (blockIdx.x == 512) {    // c = bx2 . r
        const float4* __restrict__ b4 = (const float4*)bx2;
        const float4* __restrict__ r4 = (const float4*)g_r;
        float acc = 0.0f;
#pragma unroll
        for (int k = 0; k < 4; k++) {
            float4 b = ldg4(b4 + tid + 256 * k);
            float4 r = ldg4(r4 + tid + 256 * k);
            acc += b.x * r.x + b.y * r.y + b.z * r.z + b.w * r.w;
        }
#pragma unroll
        for (int o = 16; o; o >>= 1) acc += __shfl_xor_sync(0xffffffffu, acc, o);
        __shared__ float red[8];
        if ((tid & 31) == 0) red[tid >> 5] = acc;
        __syncthreads();
        if (tid == 0) {
            float s = 0.0f;
#pragma unroll
            for (int i = 0; i < 8; i++) s += red[i];
            g_c = s;
        }
        return;
    }

    __shared__ float4 sr[RR / 4];     // 16 KB
    const float4* __restrict__ r4 = (const float4*)g_r;
#pragma unroll
    for (int k = 0; k < 4; k++)
        sr[tid + 256 * k] = r4[tid + 256 * k];
    __syncthreads();

    const int row = tid >> 7;                      // 0 or 1
    const int h = blockIdx.x * 2 + row;
    const int g = tid & 127;
    const float4* __restrict__ W4 = (const float4*)Wx2 + (size_t)h * (RR / 4) + g;

    float4 w[8];
#pragma unroll
    for (int k = 0; k < 8; k++)
        w[k] = ldg4(W4 + 128 * k);
    float acc = 0.0f;
#pragma unroll
    for (int k = 0; k < 8; k++) {
        float4 rr = sr[g + 128 * k];
        acc = fmaf(w[k].x, rr.x, acc);
        acc = fmaf(w[k].y, rr.y, acc);
        acc = fmaf(w[k].z, rr.z, acc);
        acc = fmaf(w[k].w, rr.w, acc);
    }
#pragma unroll
    for (int o = 16; o; o >>= 1) acc += __shfl_xor_sync(0xffffffffu, acc, o);
    __shared__ float part[8];
    if ((tid & 31) == 0) part[tid >> 5] = acc;
    __syncthreads();
    if (tid < 2)
        g_v[blockIdx.x * 2 + tid] = part[4 * tid] + part[4 * tid + 1] +
                                    part[4 * tid + 2] + part[4 * tid + 3];
}

// ---------------------------------------------------------------------------
// K5: out[n] = tanh(input[n] @ Wx1 + bx1) . v + c
// grid: 512 blocks x 256 threads; warp handles 4 rows n (reuses smem loads 4x)
// ---------------------------------------------------------------------------
__global__ void k5_out(const float* __restrict__ input, const float* __restrict__ Wx1,
                       const float* __restrict__ bx1, float* __restrict__ out)
{
    __shared__ float4 swb[HID];   // (w0, w1, w2, bias)
    __shared__ float  sv[HID];
    const int tid = threadIdx.x;
#pragma unroll
    for (int k = 0; k < 4; k++) {
        int h = tid + 256 * k;
        swb[h] = make_float4(Wx1[h], Wx1[HID + h], Wx1[2 * HID + h], bx1[h]);
        sv[h] = g_v[h];
    }
    __syncthreads();

    const int warp = tid >> 5, lane = tid & 31;
    const int nbase = (blockIdx.x * 8 + warp) * 4;

    float x0[4], x1[4], x2[4];
#pragma unroll
    for (int nn = 0; nn < 4; nn++) {
        x0[nn] = input[(nbase + nn) * 3 + 0];
        x1[nn] = input[(nbase + nn) * 3 + 1];
        x2[nn] = input[(nbase + nn) * 3 + 2];
    }
    float acc[4] = {0.0f, 0.0f, 0.0f, 0.0f};
#pragma unroll 4
    for (int k = 0; k < 32; k++) {
        int h = k * 32 + lane;
        float4 wb = swb[h];
        float vv = sv[h];
#pragma unroll
        for (int nn = 0; nn < 4; nn++) {
            float a = fmaf(x0[nn], wb.x, fmaf(x1[nn], wb.y, fmaf(x2[nn], wb.z, wb.w)));
            acc[nn] = fmaf(tanh_fast(a), vv, acc[nn]);
        }
    }
    float c = g_c;
#pragma unroll
    for (int nn = 0; nn < 4; nn++) {
        float a = acc[nn];
#pragma unroll
        for (int o = 16; o; o >>= 1) a += __shfl_xor_sync(0xffffffffu, a, o);
        if (lane == 0) out[nbase + nn] = a + c;
    }
}

// ---------------------------------------------------------------------------
// Input order (metadata): 0 input, 1 eq_param, 2 quad_x0, 3 quad_x1,
// 4 Wx1, 5 bx1, 6 Wx2, 7 bx2, 8 Wq0a, 9 bq0a, 10 Wq0b, 11 bq0b,
// 12 Wq1a, 13 bq1a, 14 Wq1b, 15 bq1b
// ---------------------------------------------------------------------------
extern "C" void kernel_launch(void* const* d_in, const int* in_sizes, int n_in,
                              void* d_out, int out_size)
{
    const float* input  = (const float*)d_in[0];
    const float* eq     = (const float*)d_in[1];
    const float* qx0    = (const float*)d_in[2];
    const float* qx1    = (const float*)d_in[3];
    const float* Wx1    = (const float*)d_in[4];
    const float* bx1    = (const float*)d_in[5];
    const float* Wx2    = (const float*)d_in[6];
    const float* bx2    = (const float*)d_in[7];
    const float* Wq0a   = (const float*)d_in[8];
    const float* bq0a   = (const float*)d_in[9];
    const float* Wq0b   = (const float*)d_in[10];
    const float* bq0b   = (const float*)d_in[11];
    const float* Wq1a   = (const float*)d_in[12];
    const float* bq1a   = (const float*)d_in[13];
    const float* Wq1b   = (const float*)d_in[14];
    const float* bq1b   = (const float*)d_in[15];
    float* out = (float*)d_out;

    k1_quad<<<256, 256>>>(qx0, qx1, Wq0a, bq0a, Wq1a, bq1a, eq);
    k2_S<<<512, 128>>>(Wq0b, bq0b, Wq1b, bq1b);
    k2b_reduce<<<16, 128>>>();
    k3_rhs<<<16, 256>>>();
    k4_v<<<513, 256>>>(Wx2, bx2);
    k5_out<<<512, 256>>>(input, Wx1, bx1, out);
}